// round 13
// baseline (speedup 1.0000x reference)
#include <cuda_runtime.h>
#include <cuda_fp16.h>
#include <cstdint>

#define NMAX   100000
#define NGRAPH 512
#define EMAX   1600000
#define D      128
#define SCANB  512

// ---------------- scratch (device globals) ----------------
__device__ __align__(16) __half g_x16[(size_t)NMAX * D];
__device__ __align__(16) __half g_h16[(size_t)NMAX * D];
__device__ __align__(16) __half g_m16[(size_t)NMAX * D];
__device__ __align__(16) __half g_w16[4 * D * D];
__device__ int   g_cnt[NMAX];
__device__ int   g_scan[NMAX];
__device__ int   g_bsum[(NMAX + SCANB - 1) / SCANB];
__device__ __align__(16) int g_csrc[EMAX];
__device__ int   g_rowstart[NMAX + 1];
__device__ int   g_cursor[NMAX];
__device__ __align__(16) float g_pool[NGRAPH * D];
__device__ int   g_gcnt[NGRAPH];

__device__ __forceinline__ float2 h2f2(uint32_t u) {
    __half2 h = *reinterpret_cast<__half2*>(&u);
    return __half22float2(h);
}
__device__ __forceinline__ uint32_t f2h2(float a, float b) {
    __half2 h = __floats2half2_rn(a, b);
    return *reinterpret_cast<uint32_t*>(&h);
}

// ---------------- zero cnt / pool / gcnt ----------------
__global__ void zero_kernel(int N) {
    int i = blockIdx.x * blockDim.x + threadIdx.x;
    if (i < N)          g_cnt[i]  = 0;
    if (i < NGRAPH * D) g_pool[i] = 0.f;
    if (i < NGRAPH)     g_gcnt[i] = 0;
}

// ---------------- degrees + gcnt + fp16 conversions (merged) ----------------
__global__ void prep_kernel(const int* __restrict__ ei, const int* __restrict__ batch,
                            const float* __restrict__ x, int total8,
                            const float* __restrict__ W1l, const float* __restrict__ W1r,
                            const float* __restrict__ W2l, const float* __restrict__ W2r,
                            int E, int N) {
    int i = blockIdx.x * blockDim.x + threadIdx.x;
    if (i < E) atomicAdd(&g_cnt[ei[E + i]], 1);
    if (i < N) atomicAdd(&g_gcnt[batch[i]], 1);
    if (i < total8) {
        const float4* src = (const float4*)x;
        float4 a = src[2 * i], b = src[2 * i + 1];
        uint4 o;
        o.x = f2h2(a.x, a.y); o.y = f2h2(a.z, a.w);
        o.z = f2h2(b.x, b.y); o.w = f2h2(b.z, b.w);
        ((uint4*)g_x16)[i] = o;
    }
    if (i < 8192) {
        const float* srcs[4] = {W1l, W1r, W2l, W2r};
        int mat = i / 2048;
        int off = (i % 2048) * 8;
        const float4* s = (const float4*)(srcs[mat] + off);
        float4 a = s[0], b = s[1];
        uint4 o;
        o.x = f2h2(a.x, a.y); o.y = f2h2(a.z, a.w);
        o.z = f2h2(b.x, b.y); o.w = f2h2(b.z, b.w);
        *(uint4*)(g_w16 + mat * D * D + off) = o;
    }
}

// ---------------- scan stage 1 ----------------
__global__ void scan1_kernel(int N) {
    __shared__ int sm[SCANB];
    int i = blockIdx.x * SCANB + threadIdx.x;
    int v = (i < N) ? g_cnt[i] : 0;
    sm[threadIdx.x] = v;
    __syncthreads();
    #pragma unroll
    for (int off = 1; off < SCANB; off <<= 1) {
        int t = (threadIdx.x >= off) ? sm[threadIdx.x - off] : 0;
        __syncthreads();
        sm[threadIdx.x] += t;
        __syncthreads();
    }
    if (i < N) g_scan[i] = sm[threadIdx.x];
    if (threadIdx.x == SCANB - 1) g_bsum[blockIdx.x] = sm[SCANB - 1];
}

// ---------------- scan stage 2+3 fused ----------------
__global__ void __launch_bounds__(256)
scan3_kernel(int N, int E, int NB) {
    __shared__ int red[8];
    __shared__ int s_prefix;
    const int sb = blockIdx.x >> 1;
    const int t  = threadIdx.x;
    const int lane = t & 31;
    const int wid  = t >> 5;

    int v = (t < sb && t < NB) ? g_bsum[t] : 0;
    #pragma unroll
    for (int o = 16; o; o >>= 1) v += __shfl_xor_sync(0xffffffffu, v, o);
    if (lane == 0) red[wid] = v;
    __syncthreads();
    if (t == 0) {
        int s = 0;
        #pragma unroll
        for (int w = 0; w < 8; w++) s += red[w];
        s_prefix = s;
    }
    __syncthreads();
    const int prefix = s_prefix;

    int i = blockIdx.x * 256 + t;
    if (i < N) {
        int rs = prefix + g_scan[i] - g_cnt[i];
        g_rowstart[i] = rs;
        g_cursor[i]   = rs;
    }
    if (i == 0) g_rowstart[N] = E;
}

// ---------------- edge placement into CSR ----------------
__global__ void place_kernel(const int* __restrict__ ei, int E) {
    int e = blockIdx.x * blockDim.x + threadIdx.x;
    if (e >= E) return;
    int pos = atomicAdd(&g_cursor[ei[E + e]], 1);
    g_csrc[pos] = ei[e];
}

// ---------------- gather-mean: half-warp/node, vector index loads, tiered tail --
__global__ void __launch_bounds__(256)
gather_mean16(int use_x, int N) {
    const __half* feat = use_x ? g_x16 : g_h16;
    int hw = (blockIdx.x * blockDim.x + threadIdx.x) >> 4;
    if (hw >= N) return;
    int lane = threadIdx.x & 15;
    int beg = g_rowstart[hw];
    int end = g_rowstart[hw + 1];

    float acc[8];
    #pragma unroll
    for (int q = 0; q < 8; q++) acc[q] = 0.f;

    int j = beg;
    // 8-wide tier: 2 int4 index loads (unaligned-safe: element-aligned int4 reads
    // require 16B alignment -> use two ldg.v4 only when j%4==0; otherwise peel.)
    // Peel to 4-alignment first so int4 loads are legal.
    while ((j & 3) && j < end) {
        uint4 r = *(const uint4*)(feat + (size_t)g_csrc[j] * D + lane * 8);
        float2 f0 = h2f2(r.x), f1 = h2f2(r.y), f2 = h2f2(r.z), f3 = h2f2(r.w);
        acc[0] += f0.x; acc[1] += f0.y; acc[2] += f1.x; acc[3] += f1.y;
        acc[4] += f2.x; acc[5] += f2.y; acc[6] += f3.x; acc[7] += f3.y;
        j++;
    }
    for (; j + 8 <= end; j += 8) {
        int4 i0 = *(const int4*)(g_csrc + j);
        int4 i1 = *(const int4*)(g_csrc + j + 4);
        uint4 r[8];
        r[0] = *(const uint4*)(feat + (size_t)i0.x * D + lane * 8);
        r[1] = *(const uint4*)(feat + (size_t)i0.y * D + lane * 8);
        r[2] = *(const uint4*)(feat + (size_t)i0.z * D + lane * 8);
        r[3] = *(const uint4*)(feat + (size_t)i0.w * D + lane * 8);
        r[4] = *(const uint4*)(feat + (size_t)i1.x * D + lane * 8);
        r[5] = *(const uint4*)(feat + (size_t)i1.y * D + lane * 8);
        r[6] = *(const uint4*)(feat + (size_t)i1.z * D + lane * 8);
        r[7] = *(const uint4*)(feat + (size_t)i1.w * D + lane * 8);
        #pragma unroll
        for (int u = 0; u < 8; u++) {
            float2 f0 = h2f2(r[u].x), f1 = h2f2(r[u].y);
            float2 f2 = h2f2(r[u].z), f3 = h2f2(r[u].w);
            acc[0] += f0.x; acc[1] += f0.y; acc[2] += f1.x; acc[3] += f1.y;
            acc[4] += f2.x; acc[5] += f2.y; acc[6] += f3.x; acc[7] += f3.y;
        }
    }
    if (j + 4 <= end) {
        int4 i0 = *(const int4*)(g_csrc + j);
        uint4 r[4];
        r[0] = *(const uint4*)(feat + (size_t)i0.x * D + lane * 8);
        r[1] = *(const uint4*)(feat + (size_t)i0.y * D + lane * 8);
        r[2] = *(const uint4*)(feat + (size_t)i0.z * D + lane * 8);
        r[3] = *(const uint4*)(feat + (size_t)i0.w * D + lane * 8);
        #pragma unroll
        for (int u = 0; u < 4; u++) {
            float2 f0 = h2f2(r[u].x), f1 = h2f2(r[u].y);
            float2 f2 = h2f2(r[u].z), f3 = h2f2(r[u].w);
            acc[0] += f0.x; acc[1] += f0.y; acc[2] += f1.x; acc[3] += f1.y;
            acc[4] += f2.x; acc[5] += f2.y; acc[6] += f3.x; acc[7] += f3.y;
        }
        j += 4;
    }
    for (; j < end; j++) {
        uint4 r = *(const uint4*)(feat + (size_t)g_csrc[j] * D + lane * 8);
        float2 f0 = h2f2(r.x), f1 = h2f2(r.y), f2 = h2f2(r.z), f3 = h2f2(r.w);
        acc[0] += f0.x; acc[1] += f0.y; acc[2] += f1.x; acc[3] += f1.y;
        acc[4] += f2.x; acc[5] += f2.y; acc[6] += f3.x; acc[7] += f3.y;
    }
    float invc = 1.f / fmaxf((float)(end - beg), 1.f);
    uint4 w;
    w.x = f2h2(acc[0] * invc, acc[1] * invc);
    w.y = f2h2(acc[2] * invc, acc[3] * invc);
    w.z = f2h2(acc[4] * invc, acc[5] * invc);
    w.w = f2h2(acc[6] * invc, acc[7] * invc);
    *(uint4*)(g_m16 + (size_t)hw * D + lane * 8) = w;
}

// ---------------- fp16 MMA fused SAGE linear ----------------
#define PADW 20
__global__ void __launch_bounds__(256)
gemm_sage_h(const float* __restrict__ bias, const int* __restrict__ batch,
            int layer, int N) {
    const __half* self16 = (layer == 1) ? g_x16 : g_h16;
    const __half* Wl16 = g_w16 + (layer == 1 ? 0 : 2) * D * D;
    const __half* Wr16 = Wl16 + D * D;

    __shared__ __align__(16) uint32_t As[128][PADW];
    __shared__ __align__(16) uint32_t Bs[128][PADW];

    const int tid  = threadIdx.x;
    const int warp = tid >> 5;
    const int lane = tid & 31;
    const int gq   = lane >> 2;
    const int tq   = lane & 3;
    const int wm   = (warp >> 1) * 32;
    const int wn   = (warp & 1) * 64;
    const int block_m = blockIdx.x * 128;

    float acc[2][8][4];
    #pragma unroll
    for (int mt = 0; mt < 2; mt++)
        #pragma unroll
        for (int nt = 0; nt < 8; nt++)
            #pragma unroll
            for (int r = 0; r < 4; r++) acc[mt][nt][r] = 0.f;

    for (int kc = 0; kc < 256; kc += 32) {
        const __half* A = (kc < 128) ? g_m16 : self16;
        const __half* B = (kc < 128) ? Wl16 : Wr16;
        const int kcol = kc & 127;

        #pragma unroll
        for (int it = 0; it < 2; it++) {
            int idx = tid + it * 256;
            int row = idx >> 2;
            int q   = idx & 3;
            int grow = block_m + row;
            uint4 v = make_uint4(0, 0, 0, 0);
            if (grow < N) v = *(const uint4*)(A + (size_t)grow * D + kcol + q * 8);
            *(uint4*)&As[row][q * 4] = v;
        }
        #pragma unroll
        for (int it = 0; it < 2; it++) {
            int idx = tid + it * 256;
            int row = idx >> 2;
            int q   = idx & 3;
            uint4 v = *(const uint4*)(B + (size_t)row * D + kcol + q * 8);
            *(uint4*)&Bs[row][q * 4] = v;
        }
        __syncthreads();

        #pragma unroll
        for (int ks = 0; ks < 2; ks++) {
            const int k0 = ks * 8;
            uint32_t a[2][4];
            #pragma unroll
            for (int mt = 0; mt < 2; mt++) {
                int r0 = wm + mt * 16 + gq;
                a[mt][0] = As[r0    ][k0 + tq];
                a[mt][1] = As[r0 + 8][k0 + tq];
                a[mt][2] = As[r0    ][k0 + tq + 4];
                a[mt][3] = As[r0 + 8][k0 + tq + 4];
            }
            uint32_t b[8][2];
            #pragma unroll
            for (int nt = 0; nt < 8; nt++) {
                int nr = wn + nt * 8 + gq;
                b[nt][0] = Bs[nr][k0 + tq];
                b[nt][1] = Bs[nr][k0 + tq + 4];
            }
            #pragma unroll
            for (int mt = 0; mt < 2; mt++)
                #pragma unroll
                for (int nt = 0; nt < 8; nt++)
                    asm volatile(
                        "mma.sync.aligned.m16n8k16.row.col.f32.f16.f16.f32 "
                        "{%0,%1,%2,%3},{%4,%5,%6,%7},{%8,%9},{%0,%1,%2,%3};"
                        : "+f"(acc[mt][nt][0]), "+f"(acc[mt][nt][1]),
                          "+f"(acc[mt][nt][2]), "+f"(acc[mt][nt][3])
                        : "r"(a[mt][0]), "r"(a[mt][1]), "r"(a[mt][2]), "r"(a[mt][3]),
                          "r"(b[nt][0]), "r"(b[nt][1]));
        }
        __syncthreads();
    }

    if (layer == 1) {
        #pragma unroll
        for (int nt = 0; nt < 8; nt++) {
            int col = wn + nt * 8 + 2 * tq;
            float b0 = bias[col], b1 = bias[col + 1];
            #pragma unroll
            for (int mt = 0; mt < 2; mt++) {
                int r0 = block_m + wm + mt * 16 + gq;
                int r1 = r0 + 8;
                if (r0 < N) {
                    uint32_t v = f2h2(fmaxf(acc[mt][nt][0] + b0, 0.f),
                                      fmaxf(acc[mt][nt][1] + b1, 0.f));
                    *(uint32_t*)(g_h16 + (size_t)r0 * D + col) = v;
                }
                if (r1 < N) {
                    uint32_t v = f2h2(fmaxf(acc[mt][nt][2] + b0, 0.f),
                                      fmaxf(acc[mt][nt][3] + b1, 0.f));
                    *(uint32_t*)(g_h16 + (size_t)r1 * D + col) = v;
                }
            }
        }
    } else {
        int gid0[2], gid1[2];
        #pragma unroll
        for (int mt = 0; mt < 2; mt++) {
            int r0 = block_m + wm + mt * 16 + gq;
            int r1 = r0 + 8;
            gid0[mt] = (r0 < N) ? batch[r0] : -1;
            gid1[mt] = (r1 < N) ? batch[r1] : -1;
        }
        #pragma unroll
        for (int nt = 0; nt < 8; nt++) {
            int col = wn + nt * 8 + 2 * tq;
            float b0 = bias[col], b1 = bias[col + 1];
            #pragma unroll
            for (int mt = 0; mt < 2; mt++) {
                if (gid0[mt] >= 0) {
                    float vx = fmaxf(acc[mt][nt][0] + b0, 0.f);
                    float vy = fmaxf(acc[mt][nt][1] + b1, 0.f);
                    float* p = g_pool + (size_t)gid0[mt] * D + col;
                    asm volatile("red.global.add.v2.f32 [%0], {%1,%2};"
                                 :: "l"(p), "f"(vx), "f"(vy) : "memory");
                }
                if (gid1[mt] >= 0) {
                    float vx = fmaxf(acc[mt][nt][2] + b0, 0.f);
                    float vy = fmaxf(acc[mt][nt][3] + b1, 0.f);
                    float* p = g_pool + (size_t)gid1[mt] * D + col;
                    asm volatile("red.global.add.v2.f32 [%0], {%1,%2};"
                                 :: "l"(p), "f"(vx), "f"(vy) : "memory");
                }
            }
        }
    }
}

// ---------------- head ----------------
__global__ void final_kernel(const float* __restrict__ Wf, const float* __restrict__ bf,
                             float* __restrict__ out) {
    int b = blockIdx.x;
    int lane = threadIdx.x;
    float invg = 1.f / fmaxf((float)g_gcnt[b], 1.f);
    float gm[4];
    #pragma unroll
    for (int q = 0; q < 4; q++) gm[q] = g_pool[b * D + q * 32 + lane] * invg;

    float logit[10];
    #pragma unroll
    for (int o = 0; o < 10; o++) {
        float p = 0.f;
        #pragma unroll
        for (int q = 0; q < 4; q++) p += gm[q] * Wf[o * D + q * 32 + lane];
        #pragma unroll
        for (int off = 16; off; off >>= 1) p += __shfl_xor_sync(0xffffffffu, p, off);
        logit[o] = p + bf[o];
    }
    float mx = logit[0];
    #pragma unroll
    for (int o = 1; o < 10; o++) mx = fmaxf(mx, logit[o]);
    float ssum = 0.f;
    #pragma unroll
    for (int o = 0; o < 10; o++) ssum += expf(logit[o] - mx);
    float lse = logf(ssum);
    if (lane < 10) out[b * 10 + lane] = logit[lane] - mx - lse;
}

// ---------------- launch ----------------
extern "C" void kernel_launch(void* const* d_in, const int* in_sizes, int n_in,
                              void* d_out, int out_size) {
    const float* x     = (const float*)d_in[0];
    const int*   ei    = (const int*)d_in[1];
    const int*   batch = (const int*)d_in[2];
    const float* W1l = (const float*)d_in[3];
    const float* b1  = (const float*)d_in[4];
    const float* W1r = (const float*)d_in[5];
    const float* W2l = (const float*)d_in[6];
    const float* b2  = (const float*)d_in[7];
    const float* W2r = (const float*)d_in[8];
    const float* Wf  = (const float*)d_in[9];
    const float* bf  = (const float*)d_in[10];
    float* out = (float*)d_out;

    int N = in_sizes[0] / D;
    int E = in_sizes[1] / 2;
    int G = out_size / 10;

    int tpb = 256;
    int blkN  = (N + tpb - 1) / tpb;
    int blkE  = (E + tpb - 1) / tpb;
    int NB    = (N + SCANB - 1) / SCANB;
    long long hwT = (long long)N * 16;
    int blkHW = (int)((hwT + tpb - 1) / tpb);
    int blkGemm = (N + 127) / 128;
    int total8  = N * D / 8;

    zero_kernel<<<blkN, tpb>>>(N);
    prep_kernel<<<blkE, tpb>>>(ei, batch, x, total8, W1l, W1r, W2l, W2r, E, N);
    scan1_kernel<<<NB, SCANB>>>(N);
    scan3_kernel<<<blkN, tpb>>>(N, E, NB);
    place_kernel<<<blkE, tpb>>>(ei, E);

    gather_mean16<<<blkHW, tpb>>>(1, N);
    gemm_sage_h<<<blkGemm, tpb>>>(b1, batch, /*layer=*/1, N);

    gather_mean16<<<blkHW, tpb>>>(0, N);
    gemm_sage_h<<<blkGemm, tpb>>>(b2, batch, /*layer=*/2, N);

    final_kernel<<<G, 32>>>(Wf, bf, out);
}

// round 14
// speedup vs baseline: 1.0475x; 1.0475x over previous
#include <cuda_runtime.h>
#include <cuda_fp16.h>
#include <cstdint>

#define NMAX   100000
#define NGRAPH 512
#define EMAX   1600000
#define D      128
#define SCANB  512

// ---------------- scratch (device globals) ----------------
__device__ __align__(16) __half g_x16[(size_t)NMAX * D];
__device__ __align__(16) __half g_h16[(size_t)NMAX * D];
__device__ __align__(16) __half g_m16[(size_t)NMAX * D];
__device__ __align__(16) __half g_w16[4 * D * D];
__device__ int   g_cnt[NMAX];
__device__ int   g_scan[NMAX];
__device__ int   g_bsum[(NMAX + SCANB - 1) / SCANB];
__device__ int   g_rowstart[NMAX + 1];
__device__ int   g_cursor[NMAX];
__device__ int   g_csrc[EMAX];
__device__ __align__(16) float g_pool[NGRAPH * D];
__device__ int   g_gcnt[NGRAPH];

__device__ __forceinline__ float2 h2f2(uint32_t u) {
    __half2 h = *reinterpret_cast<__half2*>(&u);
    return __half22float2(h);
}
__device__ __forceinline__ uint32_t f2h2(float a, float b) {
    __half2 h = __floats2half2_rn(a, b);
    return *reinterpret_cast<uint32_t*>(&h);
}

// ---------------- zero cnt / pool / gcnt ----------------
__global__ void zero_kernel(int N) {
    int i = blockIdx.x * blockDim.x + threadIdx.x;
    if (i < N)          g_cnt[i]  = 0;
    if (i < NGRAPH * D) g_pool[i] = 0.f;
    if (i < NGRAPH)     g_gcnt[i] = 0;
}

// ---------------- degrees + gcnt + fp16 conversions (merged, all independent) --
__global__ void prep_kernel(const int* __restrict__ ei, const int* __restrict__ batch,
                            const float* __restrict__ x, int total8,
                            const float* __restrict__ W1l, const float* __restrict__ W1r,
                            const float* __restrict__ W2l, const float* __restrict__ W2r,
                            int E, int N) {
    int i = blockIdx.x * blockDim.x + threadIdx.x;
    if (i < E) atomicAdd(&g_cnt[ei[E + i]], 1);
    if (i < N) atomicAdd(&g_gcnt[batch[i]], 1);
    if (i < total8) {
        const float4* src = (const float4*)x;
        float4 a = src[2 * i], b = src[2 * i + 1];
        uint4 o;
        o.x = f2h2(a.x, a.y); o.y = f2h2(a.z, a.w);
        o.z = f2h2(b.x, b.y); o.w = f2h2(b.z, b.w);
        ((uint4*)g_x16)[i] = o;
    }
    if (i < 8192) {
        const float* srcs[4] = {W1l, W1r, W2l, W2r};
        int mat = i / 2048;
        int off = (i % 2048) * 8;
        const float4* s = (const float4*)(srcs[mat] + off);
        float4 a = s[0], b = s[1];
        uint4 o;
        o.x = f2h2(a.x, a.y); o.y = f2h2(a.z, a.w);
        o.z = f2h2(b.x, b.y); o.w = f2h2(b.z, b.w);
        *(uint4*)(g_w16 + mat * D * D + off) = o;
    }
}

// ---------------- scan stage 1: per-block inclusive scan of g_cnt ----------------
__global__ void scan1_kernel(int N) {
    __shared__ int sm[SCANB];
    int i = blockIdx.x * SCANB + threadIdx.x;
    int v = (i < N) ? g_cnt[i] : 0;
    sm[threadIdx.x] = v;
    __syncthreads();
    #pragma unroll
    for (int off = 1; off < SCANB; off <<= 1) {
        int t = (threadIdx.x >= off) ? sm[threadIdx.x - off] : 0;
        __syncthreads();
        sm[threadIdx.x] += t;
        __syncthreads();
    }
    if (i < N) g_scan[i] = sm[threadIdx.x];
    if (threadIdx.x == SCANB - 1) g_bsum[blockIdx.x] = sm[SCANB - 1];
}

// ---------------- scan stage 2+3 fused: each block recomputes its block-prefix ---
__global__ void __launch_bounds__(256)
scan3_kernel(int N, int E, int NB) {
    __shared__ int red[8];
    __shared__ int s_prefix;
    const int sb = blockIdx.x >> 1;
    const int t  = threadIdx.x;
    const int lane = t & 31;
    const int wid  = t >> 5;

    int v = (t < sb && t < NB) ? g_bsum[t] : 0;
    #pragma unroll
    for (int o = 16; o; o >>= 1) v += __shfl_xor_sync(0xffffffffu, v, o);
    if (lane == 0) red[wid] = v;
    __syncthreads();
    if (t == 0) {
        int s = 0;
        #pragma unroll
        for (int w = 0; w < 8; w++) s += red[w];
        s_prefix = s;
    }
    __syncthreads();
    const int prefix = s_prefix;

    int i = blockIdx.x * 256 + t;
    if (i < N) {
        int rs = prefix + g_scan[i] - g_cnt[i];
        g_rowstart[i] = rs;
        g_cursor[i]   = rs;
    }
    if (i == 0) g_rowstart[N] = E;
}

// ---------------- edge placement into CSR ----------------
__global__ void place_kernel(const int* __restrict__ ei, int E) {
    int e = blockIdx.x * blockDim.x + threadIdx.x;
    if (e >= E) return;
    int pos = atomicAdd(&g_cursor[ei[E + e]], 1);
    g_csrc[pos] = ei[e];
}

// ---------------- gather-mean: half-warp per node, uint4 lanes ----------
__global__ void __launch_bounds__(256)
gather_mean16(int use_x, int N) {
    const __half* feat = use_x ? g_x16 : g_h16;
    int hw = (blockIdx.x * blockDim.x + threadIdx.x) >> 4;
    if (hw >= N) return;
    int lane = threadIdx.x & 15;
    int beg = g_rowstart[hw];
    int end = g_rowstart[hw + 1];

    float acc[8];
    #pragma unroll
    for (int q = 0; q < 8; q++) acc[q] = 0.f;

    int j = beg;
    for (; j + 8 <= end; j += 8) {
        int s[8];
        #pragma unroll
        for (int u = 0; u < 8; u++) s[u] = g_csrc[j + u];
        uint4 r[8];
        #pragma unroll
        for (int u = 0; u < 8; u++)
            r[u] = *(const uint4*)(feat + (size_t)s[u] * D + lane * 8);
        #pragma unroll
        for (int u = 0; u < 8; u++) {
            float2 f0 = h2f2(r[u].x), f1 = h2f2(r[u].y);
            float2 f2 = h2f2(r[u].z), f3 = h2f2(r[u].w);
            acc[0] += f0.x; acc[1] += f0.y; acc[2] += f1.x; acc[3] += f1.y;
            acc[4] += f2.x; acc[5] += f2.y; acc[6] += f3.x; acc[7] += f3.y;
        }
    }
    for (; j < end; j++) {
        uint4 r = *(const uint4*)(feat + (size_t)g_csrc[j] * D + lane * 8);
        float2 f0 = h2f2(r.x), f1 = h2f2(r.y);
        float2 f2 = h2f2(r.z), f3 = h2f2(r.w);
        acc[0] += f0.x; acc[1] += f0.y; acc[2] += f1.x; acc[3] += f1.y;
        acc[4] += f2.x; acc[5] += f2.y; acc[6] += f3.x; acc[7] += f3.y;
    }
    float invc = 1.f / fmaxf((float)(end - beg), 1.f);
    uint4 w;
    w.x = f2h2(acc[0] * invc, acc[1] * invc);
    w.y = f2h2(acc[2] * invc, acc[3] * invc);
    w.z = f2h2(acc[4] * invc, acc[5] * invc);
    w.w = f2h2(acc[6] * invc, acc[7] * invc);
    *(uint4*)(g_m16 + (size_t)hw * D + lane * 8) = w;
}

// ---------------- fp16 MMA fused SAGE linear ----------------
#define PADW 20
__global__ void __launch_bounds__(256)
gemm_sage_h(const float* __restrict__ bias, const int* __restrict__ batch,
            int layer, int N) {
    const __half* self16 = (layer == 1) ? g_x16 : g_h16;
    const __half* Wl16 = g_w16 + (layer == 1 ? 0 : 2) * D * D;
    const __half* Wr16 = Wl16 + D * D;

    __shared__ __align__(16) uint32_t As[128][PADW];
    __shared__ __align__(16) uint32_t Bs[128][PADW];

    const int tid  = threadIdx.x;
    const int warp = tid >> 5;
    const int lane = tid & 31;
    const int gq   = lane >> 2;
    const int tq   = lane & 3;
    const int wm   = (warp >> 1) * 32;
    const int wn   = (warp & 1) * 64;
    const int block_m = blockIdx.x * 128;

    float acc[2][8][4];
    #pragma unroll
    for (int mt = 0; mt < 2; mt++)
        #pragma unroll
        for (int nt = 0; nt < 8; nt++)
            #pragma unroll
            for (int r = 0; r < 4; r++) acc[mt][nt][r] = 0.f;

    for (int kc = 0; kc < 256; kc += 32) {
        const __half* A = (kc < 128) ? g_m16 : self16;
        const __half* B = (kc < 128) ? Wl16 : Wr16;
        const int kcol = kc & 127;

        #pragma unroll
        for (int it = 0; it < 2; it++) {
            int idx = tid + it * 256;
            int row = idx >> 2;
            int q   = idx & 3;
            int grow = block_m + row;
            uint4 v = make_uint4(0, 0, 0, 0);
            if (grow < N) v = *(const uint4*)(A + (size_t)grow * D + kcol + q * 8);
            *(uint4*)&As[row][q * 4] = v;
        }
        #pragma unroll
        for (int it = 0; it < 2; it++) {
            int idx = tid + it * 256;
            int row = idx >> 2;
            int q   = idx & 3;
            uint4 v = *(const uint4*)(B + (size_t)row * D + kcol + q * 8);
            *(uint4*)&Bs[row][q * 4] = v;
        }
        __syncthreads();

        #pragma unroll
        for (int ks = 0; ks < 2; ks++) {
            const int k0 = ks * 8;
            uint32_t a[2][4];
            #pragma unroll
            for (int mt = 0; mt < 2; mt++) {
                int r0 = wm + mt * 16 + gq;
                a[mt][0] = As[r0    ][k0 + tq];
                a[mt][1] = As[r0 + 8][k0 + tq];
                a[mt][2] = As[r0    ][k0 + tq + 4];
                a[mt][3] = As[r0 + 8][k0 + tq + 4];
            }
            uint32_t b[8][2];
            #pragma unroll
            for (int nt = 0; nt < 8; nt++) {
                int nr = wn + nt * 8 + gq;
                b[nt][0] = Bs[nr][k0 + tq];
                b[nt][1] = Bs[nr][k0 + tq + 4];
            }
            #pragma unroll
            for (int mt = 0; mt < 2; mt++)
                #pragma unroll
                for (int nt = 0; nt < 8; nt++)
                    asm volatile(
                        "mma.sync.aligned.m16n8k16.row.col.f32.f16.f16.f32 "
                        "{%0,%1,%2,%3},{%4,%5,%6,%7},{%8,%9},{%0,%1,%2,%3};"
                        : "+f"(acc[mt][nt][0]), "+f"(acc[mt][nt][1]),
                          "+f"(acc[mt][nt][2]), "+f"(acc[mt][nt][3])
                        : "r"(a[mt][0]), "r"(a[mt][1]), "r"(a[mt][2]), "r"(a[mt][3]),
                          "r"(b[nt][0]), "r"(b[nt][1]));
        }
        __syncthreads();
    }

    if (layer == 1) {
        #pragma unroll
        for (int nt = 0; nt < 8; nt++) {
            int col = wn + nt * 8 + 2 * tq;
            float b0 = bias[col], b1 = bias[col + 1];
            #pragma unroll
            for (int mt = 0; mt < 2; mt++) {
                int r0 = block_m + wm + mt * 16 + gq;
                int r1 = r0 + 8;
                if (r0 < N) {
                    uint32_t v = f2h2(fmaxf(acc[mt][nt][0] + b0, 0.f),
                                      fmaxf(acc[mt][nt][1] + b1, 0.f));
                    *(uint32_t*)(g_h16 + (size_t)r0 * D + col) = v;
                }
                if (r1 < N) {
                    uint32_t v = f2h2(fmaxf(acc[mt][nt][2] + b0, 0.f),
                                      fmaxf(acc[mt][nt][3] + b1, 0.f));
                    *(uint32_t*)(g_h16 + (size_t)r1 * D + col) = v;
                }
            }
        }
    } else {
        int gid0[2], gid1[2];
        #pragma unroll
        for (int mt = 0; mt < 2; mt++) {
            int r0 = block_m + wm + mt * 16 + gq;
            int r1 = r0 + 8;
            gid0[mt] = (r0 < N) ? batch[r0] : -1;
            gid1[mt] = (r1 < N) ? batch[r1] : -1;
        }
        #pragma unroll
        for (int nt = 0; nt < 8; nt++) {
            int col = wn + nt * 8 + 2 * tq;
            float b0 = bias[col], b1 = bias[col + 1];
            #pragma unroll
            for (int mt = 0; mt < 2; mt++) {
                if (gid0[mt] >= 0) {
                    float vx = fmaxf(acc[mt][nt][0] + b0, 0.f);
                    float vy = fmaxf(acc[mt][nt][1] + b1, 0.f);
                    float* p = g_pool + (size_t)gid0[mt] * D + col;
                    asm volatile("red.global.add.v2.f32 [%0], {%1,%2};"
                                 :: "l"(p), "f"(vx), "f"(vy) : "memory");
                }
                if (gid1[mt] >= 0) {
                    float vx = fmaxf(acc[mt][nt][2] + b0, 0.f);
                    float vy = fmaxf(acc[mt][nt][3] + b1, 0.f);
                    float* p = g_pool + (size_t)gid1[mt] * D + col;
                    asm volatile("red.global.add.v2.f32 [%0], {%1,%2};"
                                 :: "l"(p), "f"(vx), "f"(vy) : "memory");
                }
            }
        }
    }
}

// ---------------- head ----------------
__global__ void final_kernel(const float* __restrict__ Wf, const float* __restrict__ bf,
                             float* __restrict__ out) {
    int b = blockIdx.x;
    int lane = threadIdx.x;
    float invg = 1.f / fmaxf((float)g_gcnt[b], 1.f);
    float gm[4];
    #pragma unroll
    for (int q = 0; q < 4; q++) gm[q] = g_pool[b * D + q * 32 + lane] * invg;

    float logit[10];
    #pragma unroll
    for (int o = 0; o < 10; o++) {
        float p = 0.f;
        #pragma unroll
        for (int q = 0; q < 4; q++) p += gm[q] * Wf[o * D + q * 32 + lane];
        #pragma unroll
        for (int off = 16; off; off >>= 1) p += __shfl_xor_sync(0xffffffffu, p, off);
        logit[o] = p + bf[o];
    }
    float mx = logit[0];
    #pragma unroll
    for (int o = 1; o < 10; o++) mx = fmaxf(mx, logit[o]);
    float ssum = 0.f;
    #pragma unroll
    for (int o = 0; o < 10; o++) ssum += expf(logit[o] - mx);
    float lse = logf(ssum);
    if (lane < 10) out[b * 10 + lane] = logit[lane] - mx - lse;
}

// ---------------- launch ----------------
extern "C" void kernel_launch(void* const* d_in, const int* in_sizes, int n_in,
                              void* d_out, int out_size) {
    const float* x     = (const float*)d_in[0];
    const int*   ei    = (const int*)d_in[1];
    const int*   batch = (const int*)d_in[2];
    const float* W1l = (const float*)d_in[3];
    const float* b1  = (const float*)d_in[4];
    const float* W1r = (const float*)d_in[5];
    const float* W2l = (const float*)d_in[6];
    const float* b2  = (const float*)d_in[7];
    const float* W2r = (const float*)d_in[8];
    const float* Wf  = (const float*)d_in[9];
    const float* bf  = (const float*)d_in[10];
    float* out = (float*)d_out;

    int N = in_sizes[0] / D;
    int E = in_sizes[1] / 2;
    int G = out_size / 10;

    int tpb = 256;
    int blkN  = (N + tpb - 1) / tpb;
    int blkE  = (E + tpb - 1) / tpb;
    int NB    = (N + SCANB - 1) / SCANB;
    long long hwT = (long long)N * 16;
    int blkHW = (int)((hwT + tpb - 1) / tpb);
    int blkGemm = (N + 127) / 128;
    int total8  = N * D / 8;

    zero_kernel<<<blkN, tpb>>>(N);
    prep_kernel<<<blkE, tpb>>>(ei, batch, x, total8, W1l, W1r, W2l, W2r, E, N);
    scan1_kernel<<<NB, SCANB>>>(N);
    scan3_kernel<<<blkN, tpb>>>(N, E, NB);
    place_kernel<<<blkE, tpb>>>(ei, E);

    gather_mean16<<<blkHW, tpb>>>(1, N);
    gemm_sage_h<<<blkGemm, tpb>>>(b1, batch, /*layer=*/1, N);

    gather_mean16<<<blkHW, tpb>>>(0, N);
    gemm_sage_h<<<blkGemm, tpb>>>(b2, batch, /*layer=*/2, N);

    final_kernel<<<G, 32>>>(Wf, bf, out);
}

// round 15
// speedup vs baseline: 1.0550x; 1.0071x over previous
#include <cuda_runtime.h>
#include <cuda_fp16.h>
#include <cstdint>

#define NMAX   100000
#define NGRAPH 512
#define EMAX   1600000
#define D      128
#define SCANB  512

// ---------------- scratch (device globals) ----------------
__device__ __align__(16) __half g_x16[(size_t)NMAX * D];
__device__ __align__(16) __half g_h16[(size_t)NMAX * D];
__device__ __align__(16) __half g_m16[(size_t)NMAX * D];
__device__ __align__(16) __half g_w16[4 * D * D];
__device__ int   g_cnt[NMAX];
__device__ int   g_scan[NMAX];
__device__ int   g_bsum[(NMAX + SCANB - 1) / SCANB];
__device__ int   g_rowstart[NMAX + 1];
__device__ int   g_rank[EMAX];         // rank of edge within its dst list
__device__ int   g_csrc[EMAX];
__device__ __align__(16) float g_pool[NGRAPH * D];
__device__ int   g_gcnt[NGRAPH];

__device__ __forceinline__ float2 h2f2(uint32_t u) {
    __half2 h = *reinterpret_cast<__half2*>(&u);
    return __half22float2(h);
}
__device__ __forceinline__ uint32_t f2h2(float a, float b) {
    __half2 h = __floats2half2_rn(a, b);
    return *reinterpret_cast<uint32_t*>(&h);
}

// ---------------- zero cnt / pool / gcnt ----------------
__global__ void zero_kernel(int N) {
    int i = blockIdx.x * blockDim.x + threadIdx.x;
    if (i < N)          g_cnt[i]  = 0;
    if (i < NGRAPH * D) g_pool[i] = 0.f;
    if (i < NGRAPH)     g_gcnt[i] = 0;
}

// ---------------- degrees (capture rank!) + gcnt + fp16 conversions ------------
__global__ void prep_kernel(const int* __restrict__ ei, const int* __restrict__ batch,
                            const float* __restrict__ x, int total8,
                            const float* __restrict__ W1l, const float* __restrict__ W1r,
                            const float* __restrict__ W2l, const float* __restrict__ W2r,
                            int E, int N) {
    int i = blockIdx.x * blockDim.x + threadIdx.x;
    if (i < E) g_rank[i] = atomicAdd(&g_cnt[ei[E + i]], 1);   // rank within dst list
    if (i < N) atomicAdd(&g_gcnt[batch[i]], 1);
    if (i < total8) {
        const float4* src = (const float4*)x;
        float4 a = src[2 * i], b = src[2 * i + 1];
        uint4 o;
        o.x = f2h2(a.x, a.y); o.y = f2h2(a.z, a.w);
        o.z = f2h2(b.x, b.y); o.w = f2h2(b.z, b.w);
        ((uint4*)g_x16)[i] = o;
    }
    if (i < 8192) {
        const float* srcs[4] = {W1l, W1r, W2l, W2r};
        int mat = i / 2048;
        int off = (i % 2048) * 8;
        const float4* s = (const float4*)(srcs[mat] + off);
        float4 a = s[0], b = s[1];
        uint4 o;
        o.x = f2h2(a.x, a.y); o.y = f2h2(a.z, a.w);
        o.z = f2h2(b.x, b.y); o.w = f2h2(b.z, b.w);
        *(uint4*)(g_w16 + mat * D * D + off) = o;
    }
}

// ---------------- scan stage 1: per-block inclusive scan of g_cnt ----------------
__global__ void scan1_kernel(int N) {
    __shared__ int sm[SCANB];
    int i = blockIdx.x * SCANB + threadIdx.x;
    int v = (i < N) ? g_cnt[i] : 0;
    sm[threadIdx.x] = v;
    __syncthreads();
    #pragma unroll
    for (int off = 1; off < SCANB; off <<= 1) {
        int t = (threadIdx.x >= off) ? sm[threadIdx.x - off] : 0;
        __syncthreads();
        sm[threadIdx.x] += t;
        __syncthreads();
    }
    if (i < N) g_scan[i] = sm[threadIdx.x];
    if (threadIdx.x == SCANB - 1) g_bsum[blockIdx.x] = sm[SCANB - 1];
}

// ---------------- scan stage 2+3 fused: each block recomputes its block-prefix ---
__global__ void __launch_bounds__(256)
scan3_kernel(int N, int E, int NB) {
    __shared__ int red[8];
    __shared__ int s_prefix;
    const int sb = blockIdx.x >> 1;
    const int t  = threadIdx.x;
    const int lane = t & 31;
    const int wid  = t >> 5;

    int v = (t < sb && t < NB) ? g_bsum[t] : 0;
    #pragma unroll
    for (int o = 16; o; o >>= 1) v += __shfl_xor_sync(0xffffffffu, v, o);
    if (lane == 0) red[wid] = v;
    __syncthreads();
    if (t == 0) {
        int s = 0;
        #pragma unroll
        for (int w = 0; w < 8; w++) s += red[w];
        s_prefix = s;
    }
    __syncthreads();
    const int prefix = s_prefix;

    int i = blockIdx.x * 256 + t;
    if (i < N) g_rowstart[i] = prefix + g_scan[i] - g_cnt[i];
    if (i == 0) g_rowstart[N] = E;
}

// ---------------- edge placement: atomic-free (rank precomputed) ----------------
__global__ void place_kernel(const int* __restrict__ ei, int E) {
    int e = blockIdx.x * blockDim.x + threadIdx.x;
    if (e >= E) return;
    int d = ei[E + e];
    int pos = g_rowstart[d] + g_rank[e];
    g_csrc[pos] = ei[e];
}

// ---------------- gather-mean: half-warp per node, uint4 lanes ----------
__global__ void __launch_bounds__(256)
gather_mean16(int use_x, int N) {
    const __half* feat = use_x ? g_x16 : g_h16;
    int hw = (blockIdx.x * blockDim.x + threadIdx.x) >> 4;
    if (hw >= N) return;
    int lane = threadIdx.x & 15;
    int beg = g_rowstart[hw];
    int end = g_rowstart[hw + 1];

    float acc[8];
    #pragma unroll
    for (int q = 0; q < 8; q++) acc[q] = 0.f;

    int j = beg;
    for (; j + 8 <= end; j += 8) {
        int s[8];
        #pragma unroll
        for (int u = 0; u < 8; u++) s[u] = g_csrc[j + u];
        uint4 r[8];
        #pragma unroll
        for (int u = 0; u < 8; u++)
            r[u] = *(const uint4*)(feat + (size_t)s[u] * D + lane * 8);
        #pragma unroll
        for (int u = 0; u < 8; u++) {
            float2 f0 = h2f2(r[u].x), f1 = h2f2(r[u].y);
            float2 f2 = h2f2(r[u].z), f3 = h2f2(r[u].w);
            acc[0] += f0.x; acc[1] += f0.y; acc[2] += f1.x; acc[3] += f1.y;
            acc[4] += f2.x; acc[5] += f2.y; acc[6] += f3.x; acc[7] += f3.y;
        }
    }
    for (; j < end; j++) {
        uint4 r = *(const uint4*)(feat + (size_t)g_csrc[j] * D + lane * 8);
        float2 f0 = h2f2(r.x), f1 = h2f2(r.y);
        float2 f2 = h2f2(r.z), f3 = h2f2(r.w);
        acc[0] += f0.x; acc[1] += f0.y; acc[2] += f1.x; acc[3] += f1.y;
        acc[4] += f2.x; acc[5] += f2.y; acc[6] += f3.x; acc[7] += f3.y;
    }
    float invc = 1.f / fmaxf((float)(end - beg), 1.f);
    uint4 w;
    w.x = f2h2(acc[0] * invc, acc[1] * invc);
    w.y = f2h2(acc[2] * invc, acc[3] * invc);
    w.z = f2h2(acc[4] * invc, acc[5] * invc);
    w.w = f2h2(acc[6] * invc, acc[7] * invc);
    *(uint4*)(g_m16 + (size_t)hw * D + lane * 8) = w;
}

// ---------------- fp16 MMA fused SAGE linear ----------------
#define PADW 20
__global__ void __launch_bounds__(256)
gemm_sage_h(const float* __restrict__ bias, const int* __restrict__ batch,
            int layer, int N) {
    const __half* self16 = (layer == 1) ? g_x16 : g_h16;
    const __half* Wl16 = g_w16 + (layer == 1 ? 0 : 2) * D * D;
    const __half* Wr16 = Wl16 + D * D;

    __shared__ __align__(16) uint32_t As[128][PADW];
    __shared__ __align__(16) uint32_t Bs[128][PADW];

    const int tid  = threadIdx.x;
    const int warp = tid >> 5;
    const int lane = tid & 31;
    const int gq   = lane >> 2;
    const int tq   = lane & 3;
    const int wm   = (warp >> 1) * 32;
    const int wn   = (warp & 1) * 64;
    const int block_m = blockIdx.x * 128;

    float acc[2][8][4];
    #pragma unroll
    for (int mt = 0; mt < 2; mt++)
        #pragma unroll
        for (int nt = 0; nt < 8; nt++)
            #pragma unroll
            for (int r = 0; r < 4; r++) acc[mt][nt][r] = 0.f;

    for (int kc = 0; kc < 256; kc += 32) {
        const __half* A = (kc < 128) ? g_m16 : self16;
        const __half* B = (kc < 128) ? Wl16 : Wr16;
        const int kcol = kc & 127;

        #pragma unroll
        for (int it = 0; it < 2; it++) {
            int idx = tid + it * 256;
            int row = idx >> 2;
            int q   = idx & 3;
            int grow = block_m + row;
            uint4 v = make_uint4(0, 0, 0, 0);
            if (grow < N) v = *(const uint4*)(A + (size_t)grow * D + kcol + q * 8);
            *(uint4*)&As[row][q * 4] = v;
        }
        #pragma unroll
        for (int it = 0; it < 2; it++) {
            int idx = tid + it * 256;
            int row = idx >> 2;
            int q   = idx & 3;
            uint4 v = *(const uint4*)(B + (size_t)row * D + kcol + q * 8);
            *(uint4*)&Bs[row][q * 4] = v;
        }
        __syncthreads();

        #pragma unroll
        for (int ks = 0; ks < 2; ks++) {
            const int k0 = ks * 8;
            uint32_t a[2][4];
            #pragma unroll
            for (int mt = 0; mt < 2; mt++) {
                int r0 = wm + mt * 16 + gq;
                a[mt][0] = As[r0    ][k0 + tq];
                a[mt][1] = As[r0 + 8][k0 + tq];
                a[mt][2] = As[r0    ][k0 + tq + 4];
                a[mt][3] = As[r0 + 8][k0 + tq + 4];
            }
            uint32_t b[8][2];
            #pragma unroll
            for (int nt = 0; nt < 8; nt++) {
                int nr = wn + nt * 8 + gq;
                b[nt][0] = Bs[nr][k0 + tq];
                b[nt][1] = Bs[nr][k0 + tq + 4];
            }
            #pragma unroll
            for (int mt = 0; mt < 2; mt++)
                #pragma unroll
                for (int nt = 0; nt < 8; nt++)
                    asm volatile(
                        "mma.sync.aligned.m16n8k16.row.col.f32.f16.f16.f32 "
                        "{%0,%1,%2,%3},{%4,%5,%6,%7},{%8,%9},{%0,%1,%2,%3};"
                        : "+f"(acc[mt][nt][0]), "+f"(acc[mt][nt][1]),
                          "+f"(acc[mt][nt][2]), "+f"(acc[mt][nt][3])
                        : "r"(a[mt][0]), "r"(a[mt][1]), "r"(a[mt][2]), "r"(a[mt][3]),
                          "r"(b[nt][0]), "r"(b[nt][1]));
        }
        __syncthreads();
    }

    if (layer == 1) {
        #pragma unroll
        for (int nt = 0; nt < 8; nt++) {
            int col = wn + nt * 8 + 2 * tq;
            float b0 = bias[col], b1 = bias[col + 1];
            #pragma unroll
            for (int mt = 0; mt < 2; mt++) {
                int r0 = block_m + wm + mt * 16 + gq;
                int r1 = r0 + 8;
                if (r0 < N) {
                    uint32_t v = f2h2(fmaxf(acc[mt][nt][0] + b0, 0.f),
                                      fmaxf(acc[mt][nt][1] + b1, 0.f));
                    *(uint32_t*)(g_h16 + (size_t)r0 * D + col) = v;
                }
                if (r1 < N) {
                    uint32_t v = f2h2(fmaxf(acc[mt][nt][2] + b0, 0.f),
                                      fmaxf(acc[mt][nt][3] + b1, 0.f));
                    *(uint32_t*)(g_h16 + (size_t)r1 * D + col) = v;
                }
            }
        }
    } else {
        int gid0[2], gid1[2];
        #pragma unroll
        for (int mt = 0; mt < 2; mt++) {
            int r0 = block_m + wm + mt * 16 + gq;
            int r1 = r0 + 8;
            gid0[mt] = (r0 < N) ? batch[r0] : -1;
            gid1[mt] = (r1 < N) ? batch[r1] : -1;
        }
        #pragma unroll
        for (int nt = 0; nt < 8; nt++) {
            int col = wn + nt * 8 + 2 * tq;
            float b0 = bias[col], b1 = bias[col + 1];
            #pragma unroll
            for (int mt = 0; mt < 2; mt++) {
                if (gid0[mt] >= 0) {
                    float vx = fmaxf(acc[mt][nt][0] + b0, 0.f);
                    float vy = fmaxf(acc[mt][nt][1] + b1, 0.f);
                    float* p = g_pool + (size_t)gid0[mt] * D + col;
                    asm volatile("red.global.add.v2.f32 [%0], {%1,%2};"
                                 :: "l"(p), "f"(vx), "f"(vy) : "memory");
                }
                if (gid1[mt] >= 0) {
                    float vx = fmaxf(acc[mt][nt][2] + b0, 0.f);
                    float vy = fmaxf(acc[mt][nt][3] + b1, 0.f);
                    float* p = g_pool + (size_t)gid1[mt] * D + col;
                    asm volatile("red.global.add.v2.f32 [%0], {%1,%2};"
                                 :: "l"(p), "f"(vx), "f"(vy) : "memory");
                }
            }
        }
    }
}

// ---------------- head ----------------
__global__ void final_kernel(const float* __restrict__ Wf, const float* __restrict__ bf,
                             float* __restrict__ out) {
    int b = blockIdx.x;
    int lane = threadIdx.x;
    float invg = 1.f / fmaxf((float)g_gcnt[b], 1.f);
    float gm[4];
    #pragma unroll
    for (int q = 0; q < 4; q++) gm[q] = g_pool[b * D + q * 32 + lane] * invg;

    float logit[10];
    #pragma unroll
    for (int o = 0; o < 10; o++) {
        float p = 0.f;
        #pragma unroll
        for (int q = 0; q < 4; q++) p += gm[q] * Wf[o * D + q * 32 + lane];
        #pragma unroll
        for (int off = 16; off; off >>= 1) p += __shfl_xor_sync(0xffffffffu, p, off);
        logit[o] = p + bf[o];
    }
    float mx = logit[0];
    #pragma unroll
    for (int o = 1; o < 10; o++) mx = fmaxf(mx, logit[o]);
    float ssum = 0.f;
    #pragma unroll
    for (int o = 0; o < 10; o++) ssum += expf(logit[o] - mx);
    float lse = logf(ssum);
    if (lane < 10) out[b * 10 + lane] = logit[lane] - mx - lse;
}

// ---------------- launch ----------------
extern "C" void kernel_launch(void* const* d_in, const int* in_sizes, int n_in,
                              void* d_out, int out_size) {
    const float* x     = (const float*)d_in[0];
    const int*   ei    = (const int*)d_in[1];
    const int*   batch = (const int*)d_in[2];
    const float* W1l = (const float*)d_in[3];
    const float* b1  = (const float*)d_in[4];
    const float* W1r = (const float*)d_in[5];
    const float* W2l = (const float*)d_in[6];
    const float* b2  = (const float*)d_in[7];
    const float* W2r = (const float*)d_in[8];
    const float* Wf  = (const float*)d_in[9];
    const float* bf  = (const float*)d_in[10];
    float* out = (float*)d_out;

    int N = in_sizes[0] / D;
    int E = in_sizes[1] / 2;
    int G = out_size / 10;

    int tpb = 256;
    int blkN  = (N + tpb - 1) / tpb;
    int blkE  = (E + tpb - 1) / tpb;
    int NB    = (N + SCANB - 1) / SCANB;
    long long hwT = (long long)N * 16;
    int blkHW = (int)((hwT + tpb - 1) / tpb);
    int blkGemm = (N + 127) / 128;
    int total8  = N * D / 8;

    zero_kernel<<<blkN, tpb>>>(N);
    prep_kernel<<<blkE, tpb>>>(ei, batch, x, total8, W1l, W1r, W2l, W2r, E, N);
    scan1_kernel<<<NB, SCANB>>>(N);
    scan3_kernel<<<blkN, tpb>>>(N, E, NB);
    place_kernel<<<blkE, tpb>>>(ei, E);

    gather_mean16<<<blkHW, tpb>>>(1, N);
    gemm_sage_h<<<blkGemm, tpb>>>(b1, batch, /*layer=*/1, N);

    gather_mean16<<<blkHW, tpb>>>(0, N);
    gemm_sage_h<<<blkGemm, tpb>>>(b2, batch, /*layer=*/2, N);

    final_kernel<<<G, 32>>>(Wf, bf, out);
}

// round 16
// speedup vs baseline: 1.0572x; 1.0021x over previous
#include <cuda_runtime.h>
#include <cuda_fp16.h>
#include <cstdint>

#define NMAX   100000
#define NGRAPH 512
#define EMAX   1600000
#define D      128
#define SCANB  512

// ---------------- scratch (device globals; zero-init at load, kept zero by
// self-cleaning kernels: scan3 re-zeroes g_cnt, final re-zeroes g_pool/g_gcnt) --
__device__ __align__(16) __half g_x16[(size_t)NMAX * D];
__device__ __align__(16) __half g_h16[(size_t)NMAX * D];
__device__ __align__(16) __half g_m16[(size_t)NMAX * D];
__device__ __align__(16) __half g_w16[4 * D * D];
__device__ int   g_cnt[NMAX];          // invariant: zero at call entry
__device__ int   g_scan[NMAX];
__device__ int   g_bsum[(NMAX + SCANB - 1) / SCANB];
__device__ int   g_rowstart[NMAX + 1];
__device__ int   g_rank[EMAX];
__device__ int   g_csrc[EMAX];
__device__ __align__(16) float g_pool[NGRAPH * D];   // invariant: zero at entry
__device__ int   g_gcnt[NGRAPH];                     // invariant: zero at entry

__device__ __forceinline__ float2 h2f2(uint32_t u) {
    __half2 h = *reinterpret_cast<__half2*>(&u);
    return __half22float2(h);
}
__device__ __forceinline__ uint32_t f2h2(float a, float b) {
    __half2 h = __floats2half2_rn(a, b);
    return *reinterpret_cast<uint32_t*>(&h);
}

// ---------------- degrees (capture rank) + gcnt + fp16 conversions -------------
__global__ void prep_kernel(const int* __restrict__ ei, const int* __restrict__ batch,
                            const float* __restrict__ x, int total8,
                            const float* __restrict__ W1l, const float* __restrict__ W1r,
                            const float* __restrict__ W2l, const float* __restrict__ W2r,
                            int E, int N) {
    int i = blockIdx.x * blockDim.x + threadIdx.x;
    if (i < E) g_rank[i] = atomicAdd(&g_cnt[ei[E + i]], 1);   // rank within dst list
    if (i < N) atomicAdd(&g_gcnt[batch[i]], 1);
    if (i < total8) {
        const float4* src = (const float4*)x;
        float4 a = src[2 * i], b = src[2 * i + 1];
        uint4 o;
        o.x = f2h2(a.x, a.y); o.y = f2h2(a.z, a.w);
        o.z = f2h2(b.x, b.y); o.w = f2h2(b.z, b.w);
        ((uint4*)g_x16)[i] = o;
    }
    if (i < 8192) {
        const float* srcs[4] = {W1l, W1r, W2l, W2r};
        int mat = i / 2048;
        int off = (i % 2048) * 8;
        const float4* s = (const float4*)(srcs[mat] + off);
        float4 a = s[0], b = s[1];
        uint4 o;
        o.x = f2h2(a.x, a.y); o.y = f2h2(a.z, a.w);
        o.z = f2h2(b.x, b.y); o.w = f2h2(b.z, b.w);
        *(uint4*)(g_w16 + mat * D * D + off) = o;
    }
}

// ---------------- scan stage 1: per-block inclusive scan of g_cnt ----------------
__global__ void scan1_kernel(int N) {
    __shared__ int sm[SCANB];
    int i = blockIdx.x * SCANB + threadIdx.x;
    int v = (i < N) ? g_cnt[i] : 0;
    sm[threadIdx.x] = v;
    __syncthreads();
    #pragma unroll
    for (int off = 1; off < SCANB; off <<= 1) {
        int t = (threadIdx.x >= off) ? sm[threadIdx.x - off] : 0;
        __syncthreads();
        sm[threadIdx.x] += t;
        __syncthreads();
    }
    if (i < N) g_scan[i] = sm[threadIdx.x];
    if (threadIdx.x == SCANB - 1) g_bsum[blockIdx.x] = sm[SCANB - 1];
}

// ---------------- scan stage 2+3 fused; re-zeroes g_cnt (self-cleaning) ---------
__global__ void __launch_bounds__(256)
scan3_kernel(int N, int E, int NB) {
    __shared__ int red[8];
    __shared__ int s_prefix;
    const int sb = blockIdx.x >> 1;
    const int t  = threadIdx.x;
    const int lane = t & 31;
    const int wid  = t >> 5;

    int v = (t < sb && t < NB) ? g_bsum[t] : 0;
    #pragma unroll
    for (int o = 16; o; o >>= 1) v += __shfl_xor_sync(0xffffffffu, v, o);
    if (lane == 0) red[wid] = v;
    __syncthreads();
    if (t == 0) {
        int s = 0;
        #pragma unroll
        for (int w = 0; w < 8; w++) s += red[w];
        s_prefix = s;
    }
    __syncthreads();
    const int prefix = s_prefix;

    int i = blockIdx.x * 256 + t;
    if (i < N) {
        g_rowstart[i] = prefix + g_scan[i] - g_cnt[i];
        g_cnt[i] = 0;                       // restore zero invariant for next call
    }
    if (i == 0) g_rowstart[N] = E;
}

// ---------------- edge placement: atomic-free (rank precomputed) ----------------
__global__ void place_kernel(const int* __restrict__ ei, int E) {
    int e = blockIdx.x * blockDim.x + threadIdx.x;
    if (e >= E) return;
    int d = ei[E + e];
    int pos = g_rowstart[d] + g_rank[e];
    g_csrc[pos] = ei[e];
}

// ---------------- gather-mean: half-warp per node, uint4 lanes ----------
__global__ void __launch_bounds__(256)
gather_mean16(int use_x, int N) {
    const __half* feat = use_x ? g_x16 : g_h16;
    int hw = (blockIdx.x * blockDim.x + threadIdx.x) >> 4;
    if (hw >= N) return;
    int lane = threadIdx.x & 15;
    int beg = g_rowstart[hw];
    int end = g_rowstart[hw + 1];

    float acc[8];
    #pragma unroll
    for (int q = 0; q < 8; q++) acc[q] = 0.f;

    int j = beg;
    for (; j + 8 <= end; j += 8) {
        int s[8];
        #pragma unroll
        for (int u = 0; u < 8; u++) s[u] = g_csrc[j + u];
        uint4 r[8];
        #pragma unroll
        for (int u = 0; u < 8; u++)
            r[u] = *(const uint4*)(feat + (size_t)s[u] * D + lane * 8);
        #pragma unroll
        for (int u = 0; u < 8; u++) {
            float2 f0 = h2f2(r[u].x), f1 = h2f2(r[u].y);
            float2 f2 = h2f2(r[u].z), f3 = h2f2(r[u].w);
            acc[0] += f0.x; acc[1] += f0.y; acc[2] += f1.x; acc[3] += f1.y;
            acc[4] += f2.x; acc[5] += f2.y; acc[6] += f3.x; acc[7] += f3.y;
        }
    }
    for (; j < end; j++) {
        uint4 r = *(const uint4*)(feat + (size_t)g_csrc[j] * D + lane * 8);
        float2 f0 = h2f2(r.x), f1 = h2f2(r.y);
        float2 f2 = h2f2(r.z), f3 = h2f2(r.w);
        acc[0] += f0.x; acc[1] += f0.y; acc[2] += f1.x; acc[3] += f1.y;
        acc[4] += f2.x; acc[5] += f2.y; acc[6] += f3.x; acc[7] += f3.y;
    }
    float invc = 1.f / fmaxf((float)(end - beg), 1.f);
    uint4 w;
    w.x = f2h2(acc[0] * invc, acc[1] * invc);
    w.y = f2h2(acc[2] * invc, acc[3] * invc);
    w.z = f2h2(acc[4] * invc, acc[5] * invc);
    w.w = f2h2(acc[6] * invc, acc[7] * invc);
    *(uint4*)(g_m16 + (size_t)hw * D + lane * 8) = w;
}

// ---------------- fp16 MMA fused SAGE linear ----------------
#define PADW 20
__global__ void __launch_bounds__(256)
gemm_sage_h(const float* __restrict__ bias, const int* __restrict__ batch,
            int layer, int N) {
    const __half* self16 = (layer == 1) ? g_x16 : g_h16;
    const __half* Wl16 = g_w16 + (layer == 1 ? 0 : 2) * D * D;
    const __half* Wr16 = Wl16 + D * D;

    __shared__ __align__(16) uint32_t As[128][PADW];
    __shared__ __align__(16) uint32_t Bs[128][PADW];

    const int tid  = threadIdx.x;
    const int warp = tid >> 5;
    const int lane = tid & 31;
    const int gq   = lane >> 2;
    const int tq   = lane & 3;
    const int wm   = (warp >> 1) * 32;
    const int wn   = (warp & 1) * 64;
    const int block_m = blockIdx.x * 128;

    float acc[2][8][4];
    #pragma unroll
    for (int mt = 0; mt < 2; mt++)
        #pragma unroll
        for (int nt = 0; nt < 8; nt++)
            #pragma unroll
            for (int r = 0; r < 4; r++) acc[mt][nt][r] = 0.f;

    for (int kc = 0; kc < 256; kc += 32) {
        const __half* A = (kc < 128) ? g_m16 : self16;
        const __half* B = (kc < 128) ? Wl16 : Wr16;
        const int kcol = kc & 127;

        #pragma unroll
        for (int it = 0; it < 2; it++) {
            int idx = tid + it * 256;
            int row = idx >> 2;
            int q   = idx & 3;
            int grow = block_m + row;
            uint4 v = make_uint4(0, 0, 0, 0);
            if (grow < N) v = *(const uint4*)(A + (size_t)grow * D + kcol + q * 8);
            *(uint4*)&As[row][q * 4] = v;
        }
        #pragma unroll
        for (int it = 0; it < 2; it++) {
            int idx = tid + it * 256;
            int row = idx >> 2;
            int q   = idx & 3;
            uint4 v = *(const uint4*)(B + (size_t)row * D + kcol + q * 8);
            *(uint4*)&Bs[row][q * 4] = v;
        }
        __syncthreads();

        #pragma unroll
        for (int ks = 0; ks < 2; ks++) {
            const int k0 = ks * 8;
            uint32_t a[2][4];
            #pragma unroll
            for (int mt = 0; mt < 2; mt++) {
                int r0 = wm + mt * 16 + gq;
                a[mt][0] = As[r0    ][k0 + tq];
                a[mt][1] = As[r0 + 8][k0 + tq];
                a[mt][2] = As[r0    ][k0 + tq + 4];
                a[mt][3] = As[r0 + 8][k0 + tq + 4];
            }
            uint32_t b[8][2];
            #pragma unroll
            for (int nt = 0; nt < 8; nt++) {
                int nr = wn + nt * 8 + gq;
                b[nt][0] = Bs[nr][k0 + tq];
                b[nt][1] = Bs[nr][k0 + tq + 4];
            }
            #pragma unroll
            for (int mt = 0; mt < 2; mt++)
                #pragma unroll
                for (int nt = 0; nt < 8; nt++)
                    asm volatile(
                        "mma.sync.aligned.m16n8k16.row.col.f32.f16.f16.f32 "
                        "{%0,%1,%2,%3},{%4,%5,%6,%7},{%8,%9},{%0,%1,%2,%3};"
                        : "+f"(acc[mt][nt][0]), "+f"(acc[mt][nt][1]),
                          "+f"(acc[mt][nt][2]), "+f"(acc[mt][nt][3])
                        : "r"(a[mt][0]), "r"(a[mt][1]), "r"(a[mt][2]), "r"(a[mt][3]),
                          "r"(b[nt][0]), "r"(b[nt][1]));
        }
        __syncthreads();
    }

    if (layer == 1) {
        #pragma unroll
        for (int nt = 0; nt < 8; nt++) {
            int col = wn + nt * 8 + 2 * tq;
            float b0 = bias[col], b1 = bias[col + 1];
            #pragma unroll
            for (int mt = 0; mt < 2; mt++) {
                int r0 = block_m + wm + mt * 16 + gq;
                int r1 = r0 + 8;
                if (r0 < N) {
                    uint32_t v = f2h2(fmaxf(acc[mt][nt][0] + b0, 0.f),
                                      fmaxf(acc[mt][nt][1] + b1, 0.f));
                    *(uint32_t*)(g_h16 + (size_t)r0 * D + col) = v;
                }
                if (r1 < N) {
                    uint32_t v = f2h2(fmaxf(acc[mt][nt][2] + b0, 0.f),
                                      fmaxf(acc[mt][nt][3] + b1, 0.f));
                    *(uint32_t*)(g_h16 + (size_t)r1 * D + col) = v;
                }
            }
        }
    } else {
        int gid0[2], gid1[2];
        #pragma unroll
        for (int mt = 0; mt < 2; mt++) {
            int r0 = block_m + wm + mt * 16 + gq;
            int r1 = r0 + 8;
            gid0[mt] = (r0 < N) ? batch[r0] : -1;
            gid1[mt] = (r1 < N) ? batch[r1] : -1;
        }
        #pragma unroll
        for (int nt = 0; nt < 8; nt++) {
            int col = wn + nt * 8 + 2 * tq;
            float b0 = bias[col], b1 = bias[col + 1];
            #pragma unroll
            for (int mt = 0; mt < 2; mt++) {
                if (gid0[mt] >= 0) {
                    float vx = fmaxf(acc[mt][nt][0] + b0, 0.f);
                    float vy = fmaxf(acc[mt][nt][1] + b1, 0.f);
                    float* p = g_pool + (size_t)gid0[mt] * D + col;
                    asm volatile("red.global.add.v2.f32 [%0], {%1,%2};"
                                 :: "l"(p), "f"(vx), "f"(vy) : "memory");
                }
                if (gid1[mt] >= 0) {
                    float vx = fmaxf(acc[mt][nt][2] + b0, 0.f);
                    float vy = fmaxf(acc[mt][nt][3] + b1, 0.f);
                    float* p = g_pool + (size_t)gid1[mt] * D + col;
                    asm volatile("red.global.add.v2.f32 [%0], {%1,%2};"
                                 :: "l"(p), "f"(vx), "f"(vy) : "memory");
                }
            }
        }
    }
}

// ---------------- head; re-zeroes g_pool / g_gcnt (self-cleaning) ---------------
__global__ void final_kernel(const float* __restrict__ Wf, const float* __restrict__ bf,
                             float* __restrict__ out) {
    int b = blockIdx.x;
    int lane = threadIdx.x;
    float invg = 1.f / fmaxf((float)g_gcnt[b], 1.f);
    float gm[4];
    #pragma unroll
    for (int q = 0; q < 4; q++) {
        gm[q] = g_pool[b * D + q * 32 + lane] * invg;
        g_pool[b * D + q * 32 + lane] = 0.f;      // restore zero invariant
    }
    if (lane == 0) g_gcnt[b] = 0;                 // restore zero invariant

    float logit[10];
    #pragma unroll
    for (int o = 0; o < 10; o++) {
        float p = 0.f;
        #pragma unroll
        for (int q = 0; q < 4; q++) p += gm[q] * Wf[o * D + q * 32 + lane];
        #pragma unroll
        for (int off = 16; off; off >>= 1) p += __shfl_xor_sync(0xffffffffu, p, off);
        logit[o] = p + bf[o];
    }
    float mx = logit[0];
    #pragma unroll
    for (int o = 1; o < 10; o++) mx = fmaxf(mx, logit[o]);
    float ssum = 0.f;
    #pragma unroll
    for (int o = 0; o < 10; o++) ssum += expf(logit[o] - mx);
    float lse = logf(ssum);
    if (lane < 10) out[b * 10 + lane] = logit[lane] - mx - lse;
}

// ---------------- launch ----------------
extern "C" void kernel_launch(void* const* d_in, const int* in_sizes, int n_in,
                              void* d_out, int out_size) {
    const float* x     = (const float*)d_in[0];
    const int*   ei    = (const int*)d_in[1];
    const int*   batch = (const int*)d_in[2];
    const float* W1l = (const float*)d_in[3];
    const float* b1  = (const float*)d_in[4];
    const float* W1r = (const float*)d_in[5];
    const float* W2l = (const float*)d_in[6];
    const float* b2  = (const float*)d_in[7];
    const float* W2r = (const float*)d_in[8];
    const float* Wf  = (const float*)d_in[9];
    const float* bf  = (const float*)d_in[10];
    float* out = (float*)d_out;

    int N = in_sizes[0] / D;
    int E = in_sizes[1] / 2;
    int G = out_size / 10;

    int tpb = 256;
    int blkN  = (N + tpb - 1) / tpb;
    int blkE  = (E + tpb - 1) / tpb;
    int NB    = (N + SCANB - 1) / SCANB;
    long long hwT = (long long)N * 16;
    int blkHW = (int)((hwT + tpb - 1) / tpb);
    int blkGemm = (N + 127) / 128;
    int total8  = N * D / 8;

    prep_kernel<<<blkE, tpb>>>(ei, batch, x, total8, W1l, W1r, W2l, W2r, E, N);
    scan1_kernel<<<NB, SCANB>>>(N);
    scan3_kernel<<<blkN, tpb>>>(N, E, NB);
    place_kernel<<<blkE, tpb>>>(ei, E);

    gather_mean16<<<blkHW, tpb>>>(1, N);
    gemm_sage_h<<<blkGemm, tpb>>>(b1, batch, /*layer=*/1, N);

    gather_mean16<<<blkHW, tpb>>>(0, N);
    gemm_sage_h<<<blkGemm, tpb>>>(b2, batch, /*layer=*/2, N);

    final_kernel<<<G, 32>>>(Wf, bf, out);
}